// round 2
// baseline (speedup 1.0000x reference)
#include <cuda_runtime.h>
#include <cstdint>

#define NUM_NODES 16
#define HIDDEN 32
#define WARPS_PER_BLOCK 8
#define GRAPHS_PER_WARP 4

// ---------- packed f32x2 helpers (Blackwell fma.rn.f32x2, PTX-only) ----------
__device__ __forceinline__ unsigned long long fma2(unsigned long long a,
                                                   unsigned long long b,
                                                   unsigned long long c) {
    unsigned long long d;
    asm("fma.rn.f32x2 %0, %1, %2, %3;" : "=l"(d) : "l"(a), "l"(b), "l"(c));
    return d;
}
__device__ __forceinline__ unsigned long long pack2(float lo, float hi) {
    unsigned long long r;
    asm("mov.b64 %0, {%1, %2};" : "=l"(r) : "f"(lo), "f"(hi));
    return r;
}
__device__ __forceinline__ float hsum2(unsigned long long v) {
    float a, b;
    asm("mov.b64 {%0, %1}, %2;" : "=f"(a), "=f"(b) : "l"(v));
    return a + b;
}

// Per-warp smem layout (floats):
//   As  [16*17] = 272   (|z| buffer, pad-17 for conflict-free transpose read)
//   nA  [16*16] = 256   (normalized adjacency, broadcast-read rows)
//   Hs  [16*32] = 512   (hidden activations)
//   ds  [16], xs [16]
#define WARP_SMEM_FLOATS (272 + 256 + 512 + 16 + 16)   // 1072 floats = 4288 B

__global__ void __launch_bounds__(WARPS_PER_BLOCK * 32, 2)
gcn_kernel(const float* __restrict__ z,
           const float* __restrict__ node_emb,
           const float* __restrict__ spw,
           const float* __restrict__ spb,
           const float* __restrict__ alpha,
           const float* __restrict__ w1_w, const float* __restrict__ w1_b,
           const float* __restrict__ w2_w, const float* __restrict__ w2_b,
           const float* __restrict__ w3_w, const float* __restrict__ w3_b,
           const float* __restrict__ fc_w, const float* __restrict__ fc_b,
           float* __restrict__ out, int batch)
{
    __shared__ __align__(16) float smem[WARPS_PER_BLOCK * WARP_SMEM_FLOATS];

    const int wid  = threadIdx.x >> 5;
    const int l    = threadIdx.x & 31;
    const int j0   = l & 15;     // owned column of A
    const int half = l >> 4;     // row parity

    float* As = smem + wid * WARP_SMEM_FLOATS;
    float* nA = As + 272;
    float* Hs = nA + 256;
    float* ds = Hs + 512;
    float* xs = ds + 16;

    // ---- per-lane constants / weights (h = l) ----
    const float w1l = w1_w[l];
    const float b1l = w1_b[l];
    const float b2l = w2_b[l];
    const float b3l = w3_b[l];
    unsigned long long W2p[16], W3p[16];
#pragma unroll
    for (int kp = 0; kp < 16; kp++) {
        float2 v2 = *(const float2*)&w2_w[l * 32 + 2 * kp];
        W2p[kp] = pack2(v2.x, v2.y);
        float2 v3 = *(const float2*)&w3_w[l * 32 + 2 * kp];
        W3p[kp] = pack2(v3.x, v3.y);
    }
    const float fc0  = fc_w[l];
    const float fc1  = fc_w[32 + l];
    const float fcb0 = fc_b[0];
    const float fcb1 = fc_b[1];
    const float spwj = spw[j0];
    const float spb0 = spb[0];
    const float blend = 1.0f / (1.0f + expf(-alpha[0]));
    const float one_m_blend = 1.0f - blend;

    long long base_g = ((long long)blockIdx.x * WARPS_PER_BLOCK + wid) * GRAPHS_PER_WARP;

    for (int gi = 0; gi < GRAPHS_PER_WARP; gi++) {
        long long g = base_g + gi;
        if (g >= batch) break;
        const float* zg = z + g * 256;

        // ---- load |z|, stash for transpose ----
        float a[8];
#pragma unroll
        for (int k = 0; k < 8; k++) {
            a[k] = fabsf(zg[32 * k + l]);                 // element (i = 2k+half, j = j0)
            As[(2 * k + half) * 17 + j0] = a[k];
        }
        __syncwarp();

        // ---- symmetrize + min/max ----
        float ah[8];
        float mn = 1e30f, mx = -1e30f;
#pragma unroll
        for (int k = 0; k < 8; k++) {
            float s = 0.5f * (a[k] + As[j0 * 17 + 2 * k + half]);
            ah[k] = s;
            mn = fminf(mn, s);
            mx = fmaxf(mx, s);
        }
#pragma unroll
        for (int m = 16; m >= 1; m >>= 1) {
            mn = fminf(mn, __shfl_xor_sync(0xffffffffu, mn, m));
            mx = fmaxf(mx, __shfl_xor_sync(0xffffffffu, mx, m));
        }
        const float inv = 1.0f / (mx - mn + 1e-6f);

        // ---- normalize, add eye; row sums + struct projection ----
        float rsum[8], sx[8];
#pragma unroll
        for (int k = 0; k < 8; k++) {
            int i = 2 * k + half;
            float v = (ah[k] - mn) * inv + (j0 == i ? 1.0f : 0.0f);
            ah[k] = v;                       // now A_hat
            rsum[k] = v;
            sx[k] = v * spwj;
        }
#pragma unroll
        for (int m = 8; m >= 1; m >>= 1) {
#pragma unroll
            for (int k = 0; k < 8; k++) {
                rsum[k] += __shfl_xor_sync(0xffffffffu, rsum[k], m);
                sx[k]   += __shfl_xor_sync(0xffffffffu, sx[k], m);
            }
        }
        float dv[8];
#pragma unroll
        for (int k = 0; k < 8; k++) dv[k] = rsqrtf(rsum[k] + 1e-6f);

        if (j0 == 0) {
#pragma unroll
            for (int k = 0; k < 8; k++) {
                int i = 2 * k + half;
                ds[i] = dv[k];
                xs[i] = blend * (sx[k] + spb0) + one_m_blend * node_emb[i];
            }
        }
        __syncwarp();

        const float dj = ds[j0];
#pragma unroll
        for (int k = 0; k < 8; k++)
            nA[(2 * k + half) * 16 + j0] = dv[k] * ah[k] * dj;
        __syncwarp();

        // ---- Layer 1: G1[j] = xs[j]*w1[l] + b1[l] ----
        unsigned long long Gp[8];
#pragma unroll
        for (int jp = 0; jp < 8; jp++) {
            float g0 = xs[2 * jp] * w1l + b1l;
            float g1 = xs[2 * jp + 1] * w1l + b1l;
            Gp[jp] = pack2(g0, g1);
        }

        // ---- H1 = relu(nA @ G1), store to Hs ----
#pragma unroll
        for (int i = 0; i < 16; i++) {
            unsigned long long acc = 0ULL;
            const ulonglong2* row = (const ulonglong2*)(nA + i * 16);
#pragma unroll
            for (int q = 0; q < 4; q++) {
                ulonglong2 n4 = row[q];
                acc = fma2(n4.x, Gp[2 * q], acc);
                acc = fma2(n4.y, Gp[2 * q + 1], acc);
            }
            Hs[i * 32 + l] = fmaxf(hsum2(acc), 0.0f);
        }
        __syncwarp();

        // ---- Layer 2: G = Hs @ W2^T + b2 ----
        float Gv[16];
#pragma unroll
        for (int j = 0; j < 16; j++) {
            unsigned long long acc = 0ULL;
            const ulonglong2* hrow = (const ulonglong2*)(Hs + j * 32);
#pragma unroll
            for (int q = 0; q < 8; q++) {
                ulonglong2 h4 = hrow[q];
                acc = fma2(h4.x, W2p[2 * q], acc);
                acc = fma2(h4.y, W2p[2 * q + 1], acc);
            }
            Gv[j] = b2l + hsum2(acc);
        }
        __syncwarp();   // all Hs reads done before overwrite
#pragma unroll
        for (int jp = 0; jp < 8; jp++) Gp[jp] = pack2(Gv[2 * jp], Gv[2 * jp + 1]);

        // ---- H2 = relu(nA @ G2) ----
#pragma unroll
        for (int i = 0; i < 16; i++) {
            unsigned long long acc = 0ULL;
            const ulonglong2* row = (const ulonglong2*)(nA + i * 16);
#pragma unroll
            for (int q = 0; q < 4; q++) {
                ulonglong2 n4 = row[q];
                acc = fma2(n4.x, Gp[2 * q], acc);
                acc = fma2(n4.y, Gp[2 * q + 1], acc);
            }
            Hs[i * 32 + l] = fmaxf(hsum2(acc), 0.0f);
        }
        __syncwarp();

        // ---- Layer 3: G = Hs @ W3^T + b3 ----
#pragma unroll
        for (int j = 0; j < 16; j++) {
            unsigned long long acc = 0ULL;
            const ulonglong2* hrow = (const ulonglong2*)(Hs + j * 32);
#pragma unroll
            for (int q = 0; q < 8; q++) {
                ulonglong2 h4 = hrow[q];
                acc = fma2(h4.x, W3p[2 * q], acc);
                acc = fma2(h4.y, W3p[2 * q + 1], acc);
            }
            Gv[j] = b3l + hsum2(acc);
        }
        __syncwarp();
#pragma unroll
        for (int jp = 0; jp < 8; jp++) Gp[jp] = pack2(Gv[2 * jp], Gv[2 * jp + 1]);

        // ---- H3 = relu(nA @ G3); accumulate column sum (mean pool) ----
        float embsum = 0.0f;
#pragma unroll
        for (int i = 0; i < 16; i++) {
            unsigned long long acc = 0ULL;
            const ulonglong2* row = (const ulonglong2*)(nA + i * 16);
#pragma unroll
            for (int q = 0; q < 4; q++) {
                ulonglong2 n4 = row[q];
                acc = fma2(n4.x, Gp[2 * q], acc);
                acc = fma2(n4.y, Gp[2 * q + 1], acc);
            }
            embsum += fmaxf(hsum2(acc), 0.0f);
        }

        // ---- logits: reduce emb[h]*fc_w[c][h] over all 32 lanes ----
        float t0 = embsum * fc0;
        float t1 = embsum * fc1;
#pragma unroll
        for (int m = 16; m >= 1; m >>= 1) {
            t0 += __shfl_xor_sync(0xffffffffu, t0, m);
            t1 += __shfl_xor_sync(0xffffffffu, t1, m);
        }
        if (l == 0) {
            float2 o;
            o.x = t0 * 0.0625f + fcb0;   // /16 for mean
            o.y = t1 * 0.0625f + fcb1;
            *(float2*)&out[g * 2] = o;
        }
        __syncwarp();
    }
}

extern "C" void kernel_launch(void* const* d_in, const int* in_sizes, int n_in,
                              void* d_out, int out_size)
{
    const float* z     = (const float*)d_in[0];
    const float* nemb  = (const float*)d_in[1];
    const float* spw   = (const float*)d_in[2];
    const float* spb   = (const float*)d_in[3];
    const float* alpha = (const float*)d_in[4];
    const float* w1w   = (const float*)d_in[5];
    const float* w1b   = (const float*)d_in[6];
    const float* w2w   = (const float*)d_in[7];
    const float* w2b   = (const float*)d_in[8];
    const float* w3w   = (const float*)d_in[9];
    const float* w3b   = (const float*)d_in[10];
    const float* fcw   = (const float*)d_in[11];
    const float* fcb   = (const float*)d_in[12];
    float* out = (float*)d_out;

    int batch = in_sizes[0] / (NUM_NODES * NUM_NODES);
    int graphs_per_block = WARPS_PER_BLOCK * GRAPHS_PER_WARP;
    int blocks = (batch + graphs_per_block - 1) / graphs_per_block;

    gcn_kernel<<<blocks, WARPS_PER_BLOCK * 32>>>(
        z, nemb, spw, spb, alpha, w1w, w1b, w2w, w2b, w3w, w3b, fcw, fcb,
        out, batch);
}

// round 3
// speedup vs baseline: 1.0060x; 1.0060x over previous
#include <cuda_runtime.h>
#include <cstdint>

#define NUM_NODES 16
#define HIDDEN 32
#define WARPS_PER_BLOCK 8
#define GRAPHS_PER_WARP 4

// ---------- packed f32x2 helpers (Blackwell fma.rn.f32x2, PTX-only) ----------
__device__ __forceinline__ unsigned long long fma2(unsigned long long a,
                                                   unsigned long long b,
                                                   unsigned long long c) {
    unsigned long long d;
    asm("fma.rn.f32x2 %0, %1, %2, %3;" : "=l"(d) : "l"(a), "l"(b), "l"(c));
    return d;
}
__device__ __forceinline__ unsigned long long pack2(float lo, float hi) {
    unsigned long long r;
    asm("mov.b64 %0, {%1, %2};" : "=l"(r) : "f"(lo), "f"(hi));
    return r;
}
__device__ __forceinline__ float hsum2(unsigned long long v) {
    float a, b;
    asm("mov.b64 {%0, %1}, %2;" : "=f"(a), "=f"(b) : "l"(v));
    return a + b;
}

// Per-warp smem layout (floats):
//   As  [16*17] = 272   (|z| buffer, pad-17 for conflict-free transpose read)
//   nA  [16*16] = 256   (normalized adjacency, broadcast-read rows)
//   Hs  [16*32] = 512   (hidden activations)
//   ds  [16], xs [16]
#define WARP_SMEM_FLOATS (272 + 256 + 512 + 16 + 16)   // 1072 floats = 4288 B

__global__ void __launch_bounds__(WARPS_PER_BLOCK * 32, 2)
gcn_kernel(const float* __restrict__ z,
           const float* __restrict__ node_emb,
           const float* __restrict__ spw,
           const float* __restrict__ spb,
           const float* __restrict__ alpha,
           const float* __restrict__ w1_w, const float* __restrict__ w1_b,
           const float* __restrict__ w2_w, const float* __restrict__ w2_b,
           const float* __restrict__ w3_w, const float* __restrict__ w3_b,
           const float* __restrict__ fc_w, const float* __restrict__ fc_b,
           float* __restrict__ out, int batch)
{
    __shared__ __align__(16) float smem[WARPS_PER_BLOCK * WARP_SMEM_FLOATS];

    const int wid  = threadIdx.x >> 5;
    const int l    = threadIdx.x & 31;
    const int j0   = l & 15;     // owned column of A
    const int half = l >> 4;     // row parity

    float* As = smem + wid * WARP_SMEM_FLOATS;
    float* nA = As + 272;
    float* Hs = nA + 256;
    float* ds = Hs + 512;
    float* xs = ds + 16;

    // ---- per-lane constants / weights (h = l) ----
    const float w1l = w1_w[l];
    const float b1l = w1_b[l];
    const float b2l = w2_b[l];
    const float b3l = w3_b[l];
    unsigned long long W2p[16], W3p[16];
#pragma unroll
    for (int kp = 0; kp < 16; kp++) {
        float2 v2 = *(const float2*)&w2_w[l * 32 + 2 * kp];
        W2p[kp] = pack2(v2.x, v2.y);
        float2 v3 = *(const float2*)&w3_w[l * 32 + 2 * kp];
        W3p[kp] = pack2(v3.x, v3.y);
    }
    const float fc0  = fc_w[l];
    const float fc1  = fc_w[32 + l];
    const float fcb0 = fc_b[0];
    const float fcb1 = fc_b[1];
    const float spwj = spw[j0];
    const float spb0 = spb[0];
    const float blend = 1.0f / (1.0f + expf(-alpha[0]));
    const float one_m_blend = 1.0f - blend;

    long long base_g = ((long long)blockIdx.x * WARPS_PER_BLOCK + wid) * GRAPHS_PER_WARP;

    for (int gi = 0; gi < GRAPHS_PER_WARP; gi++) {
        long long g = base_g + gi;
        if (g >= batch) break;
        const float* zg = z + g * 256;

        // ---- load |z|, stash for transpose ----
        float a[8];
#pragma unroll
        for (int k = 0; k < 8; k++) {
            a[k] = fabsf(zg[32 * k + l]);                 // element (i = 2k+half, j = j0)
            As[(2 * k + half) * 17 + j0] = a[k];
        }
        __syncwarp();

        // ---- symmetrize + min/max ----
        float ah[8];
        float mn = 1e30f, mx = -1e30f;
#pragma unroll
        for (int k = 0; k < 8; k++) {
            float s = 0.5f * (a[k] + As[j0 * 17 + 2 * k + half]);
            ah[k] = s;
            mn = fminf(mn, s);
            mx = fmaxf(mx, s);
        }
#pragma unroll
        for (int m = 16; m >= 1; m >>= 1) {
            mn = fminf(mn, __shfl_xor_sync(0xffffffffu, mn, m));
            mx = fmaxf(mx, __shfl_xor_sync(0xffffffffu, mx, m));
        }
        const float inv = 1.0f / (mx - mn + 1e-6f);

        // ---- normalize, add eye; row sums + struct projection ----
        float rsum[8], sx[8];
#pragma unroll
        for (int k = 0; k < 8; k++) {
            int i = 2 * k + half;
            float v = (ah[k] - mn) * inv + (j0 == i ? 1.0f : 0.0f);
            ah[k] = v;                       // now A_hat
            rsum[k] = v;
            sx[k] = v * spwj;
        }
#pragma unroll
        for (int m = 8; m >= 1; m >>= 1) {
#pragma unroll
            for (int k = 0; k < 8; k++) {
                rsum[k] += __shfl_xor_sync(0xffffffffu, rsum[k], m);
                sx[k]   += __shfl_xor_sync(0xffffffffu, sx[k], m);
            }
        }
        float dv[8];
#pragma unroll
        for (int k = 0; k < 8; k++) dv[k] = rsqrtf(rsum[k] + 1e-6f);

        if (j0 == 0) {
#pragma unroll
            for (int k = 0; k < 8; k++) {
                int i = 2 * k + half;
                ds[i] = dv[k];
                xs[i] = blend * (sx[k] + spb0) + one_m_blend * node_emb[i];
            }
        }
        __syncwarp();

        const float dj = ds[j0];
#pragma unroll
        for (int k = 0; k < 8; k++)
            nA[(2 * k + half) * 16 + j0] = dv[k] * ah[k] * dj;
        __syncwarp();

        // ---- Layer 1: G1[j] = xs[j]*w1[l] + b1[l] ----
        unsigned long long Gp[8];
#pragma unroll
        for (int jp = 0; jp < 8; jp++) {
            float g0 = xs[2 * jp] * w1l + b1l;
            float g1 = xs[2 * jp + 1] * w1l + b1l;
            Gp[jp] = pack2(g0, g1);
        }

        // ---- H1 = relu(nA @ G1), store to Hs ----
#pragma unroll
        for (int i = 0; i < 16; i++) {
            unsigned long long acc = 0ULL;
            const ulonglong2* row = (const ulonglong2*)(nA + i * 16);
#pragma unroll
            for (int q = 0; q < 4; q++) {
                ulonglong2 n4 = row[q];
                acc = fma2(n4.x, Gp[2 * q], acc);
                acc = fma2(n4.y, Gp[2 * q + 1], acc);
            }
            Hs[i * 32 + l] = fmaxf(hsum2(acc), 0.0f);
        }
        __syncwarp();

        // ---- Layer 2: G = Hs @ W2^T + b2 ----
        float Gv[16];
#pragma unroll
        for (int j = 0; j < 16; j++) {
            unsigned long long acc = 0ULL;
            const ulonglong2* hrow = (const ulonglong2*)(Hs + j * 32);
#pragma unroll
            for (int q = 0; q < 8; q++) {
                ulonglong2 h4 = hrow[q];
                acc = fma2(h4.x, W2p[2 * q], acc);
                acc = fma2(h4.y, W2p[2 * q + 1], acc);
            }
            Gv[j] = b2l + hsum2(acc);
        }
        __syncwarp();   // all Hs reads done before overwrite
#pragma unroll
        for (int jp = 0; jp < 8; jp++) Gp[jp] = pack2(Gv[2 * jp], Gv[2 * jp + 1]);

        // ---- H2 = relu(nA @ G2) ----
#pragma unroll
        for (int i = 0; i < 16; i++) {
            unsigned long long acc = 0ULL;
            const ulonglong2* row = (const ulonglong2*)(nA + i * 16);
#pragma unroll
            for (int q = 0; q < 4; q++) {
                ulonglong2 n4 = row[q];
                acc = fma2(n4.x, Gp[2 * q], acc);
                acc = fma2(n4.y, Gp[2 * q + 1], acc);
            }
            Hs[i * 32 + l] = fmaxf(hsum2(acc), 0.0f);
        }
        __syncwarp();

        // ---- Layer 3: G = Hs @ W3^T + b3 ----
#pragma unroll
        for (int j = 0; j < 16; j++) {
            unsigned long long acc = 0ULL;
            const ulonglong2* hrow = (const ulonglong2*)(Hs + j * 32);
#pragma unroll
            for (int q = 0; q < 8; q++) {
                ulonglong2 h4 = hrow[q];
                acc = fma2(h4.x, W3p[2 * q], acc);
                acc = fma2(h4.y, W3p[2 * q + 1], acc);
            }
            Gv[j] = b3l + hsum2(acc);
        }
        __syncwarp();
#pragma unroll
        for (int jp = 0; jp < 8; jp++) Gp[jp] = pack2(Gv[2 * jp], Gv[2 * jp + 1]);

        // ---- H3 = relu(nA @ G3); accumulate column sum (mean pool) ----
        float embsum = 0.0f;
#pragma unroll
        for (int i = 0; i < 16; i++) {
            unsigned long long acc = 0ULL;
            const ulonglong2* row = (const ulonglong2*)(nA + i * 16);
#pragma unroll
            for (int q = 0; q < 4; q++) {
                ulonglong2 n4 = row[q];
                acc = fma2(n4.x, Gp[2 * q], acc);
                acc = fma2(n4.y, Gp[2 * q + 1], acc);
            }
            embsum += fmaxf(hsum2(acc), 0.0f);
        }

        // ---- logits: reduce emb[h]*fc_w[c][h] over all 32 lanes ----
        float t0 = embsum * fc0;
        float t1 = embsum * fc1;
#pragma unroll
        for (int m = 16; m >= 1; m >>= 1) {
            t0 += __shfl_xor_sync(0xffffffffu, t0, m);
            t1 += __shfl_xor_sync(0xffffffffu, t1, m);
        }
        if (l == 0) {
            float2 o;
            o.x = t0 * 0.0625f + fcb0;   // /16 for mean
            o.y = t1 * 0.0625f + fcb1;
            *(float2*)&out[g * 2] = o;
        }
        __syncwarp();
    }
}

extern "C" void kernel_launch(void* const* d_in, const int* in_sizes, int n_in,
                              void* d_out, int out_size)
{
    const float* z     = (const float*)d_in[0];
    const float* nemb  = (const float*)d_in[1];
    const float* spw   = (const float*)d_in[2];
    const float* spb   = (const float*)d_in[3];
    const float* alpha = (const float*)d_in[4];
    const float* w1w   = (const float*)d_in[5];
    const float* w1b   = (const float*)d_in[6];
    const float* w2w   = (const float*)d_in[7];
    const float* w2b   = (const float*)d_in[8];
    const float* w3w   = (const float*)d_in[9];
    const float* w3b   = (const float*)d_in[10];
    const float* fcw   = (const float*)d_in[11];
    const float* fcb   = (const float*)d_in[12];
    float* out = (float*)d_out;

    int batch = in_sizes[0] / (NUM_NODES * NUM_NODES);
    int graphs_per_block = WARPS_PER_BLOCK * GRAPHS_PER_WARP;
    int blocks = (batch + graphs_per_block - 1) / graphs_per_block;

    gcn_kernel<<<blocks, WARPS_PER_BLOCK * 32>>>(
        z, nemb, spw, spb, alpha, w1w, w1b, w2w, w2b, w3w, w3b, fcw, fcb,
        out, batch);
}

// round 4
// speedup vs baseline: 1.6160x; 1.6063x over previous
#include <cuda_runtime.h>
#include <cstdint>

#define WPB 4            // warps per block
#define SERIAL 2         // serial graph-pairs per warp (4 graphs/warp total)
#define GSTRIDE 784      // floats per graph smem region (== 16 mod 32 for bank disjointness)
#define WROW 36          // W smem row stride in floats (2-way conflict max, 16B aligned)

// ---------- packed f32x2 helpers (Blackwell fma.rn.f32x2, PTX-only) ----------
__device__ __forceinline__ unsigned long long fma2(unsigned long long a,
                                                   unsigned long long b,
                                                   unsigned long long c) {
    unsigned long long d;
    asm("fma.rn.f32x2 %0, %1, %2, %3;" : "=l"(d) : "l"(a), "l"(b), "l"(c));
    return d;
}
__device__ __forceinline__ unsigned long long pack2(float lo, float hi) {
    unsigned long long r;
    asm("mov.b64 %0, {%1, %2};" : "=l"(r) : "f"(lo), "f"(hi));
    return r;
}
__device__ __forceinline__ float hsum2(unsigned long long v) {
    float a, b;
    asm("mov.b64 {%0, %1}, %2;" : "=f"(a), "=f"(b) : "l"(v));
    return a + b;
}

// H[i][slots] = relu(nA_row_i . G), written to HS as (h0,h1) pair at slot 2*j0
__device__ __forceinline__ void propagate_store(const float* __restrict__ NA,
                                                float* __restrict__ HS,
                                                const unsigned long long* Gp0,
                                                const unsigned long long* Gp1,
                                                int j0) {
#pragma unroll
    for (int i = 0; i < 16; i++) {
        const ulonglong2* nr = (const ulonglong2*)(NA + i * 16);
        ulonglong2 n0 = nr[0], n1 = nr[1], n2 = nr[2], n3 = nr[3];
        unsigned long long a0 = 0ULL, a1 = 0ULL;
        a0 = fma2(n0.x, Gp0[0], a0); a0 = fma2(n0.y, Gp0[1], a0);
        a0 = fma2(n1.x, Gp0[2], a0); a0 = fma2(n1.y, Gp0[3], a0);
        a0 = fma2(n2.x, Gp0[4], a0); a0 = fma2(n2.y, Gp0[5], a0);
        a0 = fma2(n3.x, Gp0[6], a0); a0 = fma2(n3.y, Gp0[7], a0);
        a1 = fma2(n0.x, Gp1[0], a1); a1 = fma2(n0.y, Gp1[1], a1);
        a1 = fma2(n1.x, Gp1[2], a1); a1 = fma2(n1.y, Gp1[3], a1);
        a1 = fma2(n2.x, Gp1[4], a1); a1 = fma2(n2.y, Gp1[5], a1);
        a1 = fma2(n3.x, Gp1[6], a1); a1 = fma2(n3.y, Gp1[7], a1);
        float h0 = fmaxf(hsum2(a0), 0.0f);
        float h1 = fmaxf(hsum2(a1), 0.0f);
        *(unsigned long long*)(HS + i * 32 + 2 * j0) = pack2(h0, h1);
    }
}

// Last layer: accumulate column sums for mean pooling instead of storing.
__device__ __forceinline__ void propagate_pool(const float* __restrict__ NA,
                                               const unsigned long long* Gp0,
                                               const unsigned long long* Gp1,
                                               float& e0, float& e1) {
#pragma unroll
    for (int i = 0; i < 16; i++) {
        const ulonglong2* nr = (const ulonglong2*)(NA + i * 16);
        ulonglong2 n0 = nr[0], n1 = nr[1], n2 = nr[2], n3 = nr[3];
        unsigned long long a0 = 0ULL, a1 = 0ULL;
        a0 = fma2(n0.x, Gp0[0], a0); a0 = fma2(n0.y, Gp0[1], a0);
        a0 = fma2(n1.x, Gp0[2], a0); a0 = fma2(n1.y, Gp0[3], a0);
        a0 = fma2(n2.x, Gp0[4], a0); a0 = fma2(n2.y, Gp0[5], a0);
        a0 = fma2(n3.x, Gp0[6], a0); a0 = fma2(n3.y, Gp0[7], a0);
        a1 = fma2(n0.x, Gp1[0], a1); a1 = fma2(n0.y, Gp1[1], a1);
        a1 = fma2(n1.x, Gp1[2], a1); a1 = fma2(n1.y, Gp1[3], a1);
        a1 = fma2(n2.x, Gp1[4], a1); a1 = fma2(n2.y, Gp1[5], a1);
        a1 = fma2(n3.x, Gp1[6], a1); a1 = fma2(n3.y, Gp1[7], a1);
        e0 += fmaxf(hsum2(a0), 0.0f);
        e1 += fmaxf(hsum2(a1), 0.0f);
    }
}

// G[j][h] = sum_k H[j][k]*W[h][k] + b, for h = j0 and j0+16, packed over j-pairs.
__device__ __forceinline__ void hw_layer(const float* __restrict__ HS,
                                         const float* __restrict__ Wbase,
                                         int j0, float bh0, float bh1,
                                         unsigned long long* Gp0,
                                         unsigned long long* Gp1) {
    const ulonglong2* w0r = (const ulonglong2*)(Wbase + j0 * WROW);
    const ulonglong2* w1r = (const ulonglong2*)(Wbase + (j0 + 16) * WROW);
    ulonglong2 W0[8], W1[8];
#pragma unroll
    for (int q = 0; q < 8; q++) { W0[q] = w0r[q]; W1[q] = w1r[q]; }
#pragma unroll
    for (int j = 0; j < 16; j += 2) {
        float g00, g01, g10, g11;
        {
            const ulonglong2* hr = (const ulonglong2*)(HS + j * 32);
            unsigned long long a0 = 0ULL, a1 = 0ULL;
#pragma unroll
            for (int q = 0; q < 8; q++) {
                ulonglong2 h = hr[q];
                a0 = fma2(h.x, W0[q].x, a0); a0 = fma2(h.y, W0[q].y, a0);
                a1 = fma2(h.x, W1[q].x, a1); a1 = fma2(h.y, W1[q].y, a1);
            }
            g00 = bh0 + hsum2(a0);
            g10 = bh1 + hsum2(a1);
        }
        {
            const ulonglong2* hr = (const ulonglong2*)(HS + (j + 1) * 32);
            unsigned long long a0 = 0ULL, a1 = 0ULL;
#pragma unroll
            for (int q = 0; q < 8; q++) {
                ulonglong2 h = hr[q];
                a0 = fma2(h.x, W0[q].x, a0); a0 = fma2(h.y, W0[q].y, a0);
                a1 = fma2(h.x, W1[q].x, a1); a1 = fma2(h.y, W1[q].y, a1);
            }
            g01 = bh0 + hsum2(a0);
            g11 = bh1 + hsum2(a1);
        }
        Gp0[j >> 1] = pack2(g00, g01);
        Gp1[j >> 1] = pack2(g10, g11);
    }
}

__global__ void __launch_bounds__(WPB * 32)
gcn_kernel(const float* __restrict__ z,
           const float* __restrict__ node_emb,
           const float* __restrict__ spw,
           const float* __restrict__ spb,
           const float* __restrict__ alpha,
           const float* __restrict__ w1_w, const float* __restrict__ w1_b,
           const float* __restrict__ w2_w, const float* __restrict__ w2_b,
           const float* __restrict__ w3_w, const float* __restrict__ w3_b,
           const float* __restrict__ fc_w, const float* __restrict__ fc_b,
           float* __restrict__ out, int batch)
{
    __shared__ __align__(16) float gsm[WPB * 2 * GSTRIDE];   // per-graph regions
    __shared__ __align__(16) float Wsm[2 * 32 * WROW];       // W2, W3 slot-interleaved
    __shared__ float nesm[16];

    const int tid = threadIdx.x;

    // Stage W2/W3 into smem, columns permuted to slot order: slot 2t <- k=t, slot 2t+1 <- k=t+16
    for (int idx = tid; idx < 2 * 32 * 16; idx += WPB * 32) {
        int m = idx >> 9;            // 0 = W2, 1 = W3
        int rem = idx & 511;
        int h = rem >> 4;
        int t = rem & 15;
        const float* w = m ? w3_w : w2_w;
        float* dst = Wsm + m * 32 * WROW + h * WROW + 2 * t;
        dst[0] = w[h * 32 + t];
        dst[1] = w[h * 32 + t + 16];
    }
    if (tid < 16) nesm[tid] = node_emb[tid];
    __syncthreads();

    const int wid  = tid >> 5;
    const int l    = tid & 31;
    const int j0   = l & 15;      // owned node column AND hidden pair (j0, j0+16)
    const int gsel = l >> 4;      // which of the 2 concurrent graphs

    float* GR = gsm + (wid * 2 + gsel) * GSTRIDE;
    float* AS = GR;               // 16x20 transpose buffer (prep only)
    float* HS = GR;               // 16x32 hidden, aliases AS after prep
    float* NA = GR + 512;         // 16x16 normalized adjacency

    // lane constants
    const float w1h0 = w1_w[j0], w1h1 = w1_w[j0 + 16];
    const unsigned long long w1p0 = pack2(w1h0, w1h0);
    const unsigned long long w1p1 = pack2(w1h1, w1h1);
    const unsigned long long b1p0 = pack2(w1_b[j0], w1_b[j0]);
    const unsigned long long b1p1 = pack2(w1_b[j0 + 16], w1_b[j0 + 16]);
    const float b2h0 = w2_b[j0], b2h1 = w2_b[j0 + 16];
    const float b3h0 = w3_b[j0], b3h1 = w3_b[j0 + 16];
    const float fc00 = fc_w[j0], fc01 = fc_w[j0 + 16];
    const float fc10 = fc_w[32 + j0], fc11 = fc_w[32 + j0 + 16];
    const float fcb0 = fc_b[0], fcb1 = fc_b[1];
    const float spwj = spw[j0], spb0 = spb[0];
    const float blend = 1.0f / (1.0f + expf(-alpha[0]));
    const float omb = 1.0f - blend;

    long long warpbase = ((long long)blockIdx.x * WPB + wid) * (SERIAL * 2);

    for (int si = 0; si < SERIAL; si++) {
        long long g = warpbase + si * 2 + gsel;
        const bool valid = (g < batch);
        const float* zg = z + (valid ? g : 0) * 256;

        // ---- load |z| row j0 (lane holds row; coalesced across half-warp) ----
        float ar[16];
        const float4* zr = (const float4*)(zg + j0 * 16);
#pragma unroll
        for (int q = 0; q < 4; q++) {
            float4 v = zr[q];
            ar[4 * q]     = fabsf(v.x);
            ar[4 * q + 1] = fabsf(v.y);
            ar[4 * q + 2] = fabsf(v.z);
            ar[4 * q + 3] = fabsf(v.w);
        }
        // scatter-store transposed: AS[i][j0] = |z[j0][i]|
#pragma unroll
        for (int i = 0; i < 16; i++) AS[i * 20 + j0] = ar[i];
        __syncwarp();

        // read own AS row -> column j0 of |z|; symmetrize
        float s[16];
        float mn = 1e30f, mx = -1e30f;
        const float4* asr = (const float4*)(AS + j0 * 20);
#pragma unroll
        for (int q = 0; q < 4; q++) {
            float4 c = asr[q];
            s[4 * q]     = 0.5f * (ar[4 * q]     + c.x);
            s[4 * q + 1] = 0.5f * (ar[4 * q + 1] + c.y);
            s[4 * q + 2] = 0.5f * (ar[4 * q + 2] + c.z);
            s[4 * q + 3] = 0.5f * (ar[4 * q + 3] + c.w);
        }
#pragma unroll
        for (int i = 0; i < 16; i++) { mn = fminf(mn, s[i]); mx = fmaxf(mx, s[i]); }
#pragma unroll
        for (int m = 8; m >= 1; m >>= 1) {
            mn = fminf(mn, __shfl_xor_sync(0xffffffffu, mn, m));
            mx = fmaxf(mx, __shfl_xor_sync(0xffffffffu, mx, m));
        }
        const float inv = 1.0f / (mx - mn + 1e-6f);

        // normalize + eye; per-lane partials for row sums & struct projection
        float rs[16], sx[16];
#pragma unroll
        for (int i = 0; i < 16; i++) {
            float v = (s[i] - mn) * inv + (i == j0 ? 1.0f : 0.0f);
            s[i] = v;
            rs[i] = v;
            sx[i] = v * spwj;
        }
        // butterfly-sum across the 16-lane group: every lane gets full D and struct_x
#pragma unroll
        for (int m = 8; m >= 1; m >>= 1) {
#pragma unroll
            for (int i = 0; i < 16; i++) {
                rs[i] += __shfl_xor_sync(0xffffffffu, rs[i], m);
                sx[i] += __shfl_xor_sync(0xffffffffu, sx[i], m);
            }
        }
        float d[16], dj = 0.0f;
#pragma unroll
        for (int i = 0; i < 16; i++) {
            d[i] = rsqrtf(rs[i] + 1e-6f);
            if (i == j0) dj = d[i];
        }
        float X[16];
#pragma unroll
        for (int i = 0; i < 16; i++) {
            NA[i * 16 + j0] = d[i] * s[i] * dj;
            X[i] = blend * (sx[i] + spb0) + omb * nesm[i];
        }
        __syncwarp();

        // ---- layer 1: G1 packed over node-pairs for both hidden units ----
        unsigned long long Gp0[8], Gp1[8];
#pragma unroll
        for (int jp = 0; jp < 8; jp++) {
            unsigned long long Xp = pack2(X[2 * jp], X[2 * jp + 1]);
            Gp0[jp] = fma2(Xp, w1p0, b1p0);
            Gp1[jp] = fma2(Xp, w1p1, b1p1);
        }

        propagate_store(NA, HS, Gp0, Gp1, j0);   // H1 -> HS (overwrites AS; reads done)
        __syncwarp();

        hw_layer(HS, Wsm, j0, b2h0, b2h1, Gp0, Gp1);          // G2
        __syncwarp();                                         // all HS reads done
        propagate_store(NA, HS, Gp0, Gp1, j0);                // H2 -> HS
        __syncwarp();

        hw_layer(HS, Wsm + 32 * WROW, j0, b3h0, b3h1, Gp0, Gp1);  // G3
        __syncwarp();                                             // HS reads done

        float e0 = 0.0f, e1 = 0.0f;
        propagate_pool(NA, Gp0, Gp1, e0, e1);                 // H3 column sums

        // ---- logits ----
        float t0 = e0 * fc00 + e1 * fc01;
        float t1 = e0 * fc10 + e1 * fc11;
#pragma unroll
        for (int m = 8; m >= 1; m >>= 1) {
            t0 += __shfl_xor_sync(0xffffffffu, t0, m);
            t1 += __shfl_xor_sync(0xffffffffu, t1, m);
        }
        if (j0 == 0 && valid) {
            float2 o;
            o.x = t0 * 0.0625f + fcb0;
            o.y = t1 * 0.0625f + fcb1;
            *(float2*)(out + g * 2) = o;
        }
        __syncwarp();
    }
}

extern "C" void kernel_launch(void* const* d_in, const int* in_sizes, int n_in,
                              void* d_out, int out_size)
{
    const float* z     = (const float*)d_in[0];
    const float* nemb  = (const float*)d_in[1];
    const float* spw   = (const float*)d_in[2];
    const float* spb   = (const float*)d_in[3];
    const float* alpha = (const float*)d_in[4];
    const float* w1w   = (const float*)d_in[5];
    const float* w1b   = (const float*)d_in[6];
    const float* w2w   = (const float*)d_in[7];
    const float* w2b   = (const float*)d_in[8];
    const float* w3w   = (const float*)d_in[9];
    const float* w3b   = (const float*)d_in[10];
    const float* fcw   = (const float*)d_in[11];
    const float* fcb   = (const float*)d_in[12];
    float* out = (float*)d_out;

    int batch = in_sizes[0] / 256;
    int graphs_per_block = WPB * SERIAL * 2;
    int blocks = (batch + graphs_per_block - 1) / graphs_per_block;

    gcn_kernel<<<blocks, WPB * 32>>>(
        z, nemb, spw, spb, alpha, w1w, w1b, w2w, w2b, w3w, w3b, fcw, fcb,
        out, batch);
}